// round 7
// baseline (speedup 1.0000x reference)
#include <cuda_runtime.h>
#include <math.h>
#include <stdint.h>

// Backflow transform, periodic box — single fused kernel, 2-CTA clusters.
//   Each block: wraps its 1024-particle j-half from raw x (divide matches the
//   reference's floor(x/L) bitwise), runs the packed-f32x2 pair loop for its
//   32-i tile, reduces across 4 warps. The two j-half blocks of an i-tile form
//   a cluster: rank 1 pushes partials into rank 0's smem (DSMEM), one cluster
//   barrier, rank 0 combines in fixed order (p0+p1) and writes the output.
// fr(d) = 0.5*(exp(-(b/d)^5) - 1); exp via 2^(Cb * rsqrt(r2u)^5), box units,
// Cb = -(b/L)^5*log2(e). Diagonal: r2=0 -> ex2(-inf)=0 -> s=-0.5, times 0 -> 0.
// rint via magic 1.5*2^23 (exact RNE for |t|<1; |du|<1 in box units).

#define NPART  2048
#define NBATCH 8
#define TPB    128
#define NWARP  4
#define ITILE  32
#define JHALF  (NPART / 2)               // 1024 j's per block
#define JW     (JHALF / NWARP)           // 256 j's per warp -> 128 packed iters
#define NTILE  (NPART / ITILE)           // 64 i-tiles per batch
#define NBLK   (NBATCH * NTILE * 2)      // 1024 blocks = 512 clusters

typedef unsigned long long u64;

__device__ __forceinline__ u64 pk2(float lo, float hi) {
    u64 r; asm("mov.b64 %0, {%1,%2};" : "=l"(r) : "f"(lo), "f"(hi)); return r;
}
__device__ __forceinline__ void upk2(u64 v, float& lo, float& hi) {
    asm("mov.b64 {%0,%1}, %2;" : "=f"(lo), "=f"(hi) : "l"(v));
}
__device__ __forceinline__ u64 fma2_(u64 a, u64 b, u64 c) {
    u64 d; asm("fma.rn.f32x2 %0,%1,%2,%3;" : "=l"(d) : "l"(a), "l"(b), "l"(c)); return d;
}
__device__ __forceinline__ u64 add2_(u64 a, u64 b) {
    u64 d; asm("add.rn.f32x2 %0,%1,%2;" : "=l"(d) : "l"(a), "l"(b)); return d;
}
__device__ __forceinline__ u64 sub2_(u64 a, u64 b) {
    u64 d; asm("sub.rn.f32x2 %0,%1,%2;" : "=l"(d) : "l"(a), "l"(b)); return d;
}
__device__ __forceinline__ u64 mul2_(u64 a, u64 b) {
    u64 d; asm("mul.rn.f32x2 %0,%1,%2;" : "=l"(d) : "l"(a), "l"(b)); return d;
}
__device__ __forceinline__ float ex2f(float x) {
    float r; asm("ex2.approx.ftz.f32 %0, %1;" : "=f"(r) : "f"(x)); return r;
}
__device__ __forceinline__ float rsq_(float x) {
    float r; asm("rsqrt.approx.ftz.f32 %0, %1;" : "=f"(r) : "f"(x)); return r;
}

#define MAGICF 12582912.0f  // 1.5 * 2^23

__global__ __launch_bounds__(TPB, 8) __cluster_dims__(2, 1, 1)
void backflow_kernel(const float* __restrict__ x, float* __restrict__ out,
                     float Lf, float invLf, float Cb)
{
    __shared__ __align__(16) float sx[JHALF];   // own j-half, negated, box units
    __shared__ __align__(16) float sy[JHALF];
    __shared__ __align__(16) float sz[JHALF];
    __shared__ float red[NWARP][3][ITILE];      // per-warp partials
    __shared__ float fin[3][ITILE];             // rank 0: own-half combined partial
    __shared__ float p1buf[3][ITILE];           // rank 0: partner-half partial (DSMEM)
    __shared__ float uio[3][ITILE];             // i-tile wrapped coords (positive)

    const int blk   = blockIdx.x;
    const int b     = blk >> 7;                 // batch
    const int rem   = blk & 127;
    const int itile = rem >> 1;
    const int half  = rem & 1;                  // == cluster rank (consecutive bids)
    const int pbase = b * NPART;
    const int jbase = pbase + half * JHALF;

    // Wrap own j-half into smem (negated box units). Divide matches reference.
    for (int k = threadIdx.x; k < JHALF; k += TPB) {
        const int p = jbase + k;
        float xx = x[3 * p + 0];
        float yy = x[3 * p + 1];
        float zz = x[3 * p + 2];
        xx -= Lf * floorf(xx / Lf);
        yy -= Lf * floorf(yy / Lf);
        zz -= Lf * floorf(zz / Lf);
        sx[k] = -xx * invLf; sy[k] = -yy * invLf; sz[k] = -zz * invLf;
    }
    // Wrap the 32 i-coords (positive box units).
    if (threadIdx.x < ITILE) {
        const int p = pbase + itile * ITILE + threadIdx.x;
        float xx = x[3 * p + 0];
        float yy = x[3 * p + 1];
        float zz = x[3 * p + 2];
        xx -= Lf * floorf(xx / Lf);
        yy -= Lf * floorf(yy / Lf);
        zz -= Lf * floorf(zz / Lf);
        uio[0][threadIdx.x] = xx * invLf;
        uio[1][threadIdx.x] = yy * invLf;
        uio[2][threadIdx.x] = zz * invLf;
    }
    __syncthreads();

    const int lane = threadIdx.x & 31;
    const int w    = threadIdx.x >> 5;

    const float ux = uio[0][lane], uy = uio[1][lane], uz = uio[2][lane];
    const u64 xix = pk2(ux, ux);
    const u64 xiy = pk2(uy, uy);
    const u64 xiz = pk2(uz, uz);
    const u64 MAG2  = pk2(MAGICF, MAGICF);
    const u64 NMAG2 = pk2(-MAGICF, -MAGICF);
    const u64 C2    = pk2(Cb, Cb);
    const u64 H2    = pk2(0.5f, 0.5f);
    const u64 NH2   = pk2(-0.5f, -0.5f);

    const u64* __restrict__ sx2 = (const u64*)sx;
    const u64* __restrict__ sy2 = (const u64*)sy;
    const u64* __restrict__ sz2 = (const u64*)sz;

    u64 axp = 0ull, ayp = 0ull, azp = 0ull;

    const int base = (w * JW) >> 1;
    #pragma unroll 4
    for (int jj = 0; jj < JW / 2; ++jj) {
        // All lanes read the same address -> LDS.64 broadcast, conflict-free.
        u64 nxj = sx2[base + jj];               // (-uj0, -uj1)
        u64 nyj = sy2[base + jj];
        u64 nzj = sz2[base + jj];
        u64 dx = add2_(xix, nxj);               // ui - uj, two pairs at once
        u64 dy = add2_(xiy, nyj);
        u64 dz = add2_(xiz, nzj);
        // minimum image in box units: d -= rint(d)
        u64 tx = add2_(dx, MAG2);
        u64 ty = add2_(dy, MAG2);
        u64 tz = add2_(dz, MAG2);
        u64 rx = add2_(tx, NMAG2);
        u64 ry = add2_(ty, NMAG2);
        u64 rz = add2_(tz, NMAG2);
        dx = sub2_(dx, rx);
        dy = sub2_(dy, ry);
        dz = sub2_(dz, rz);
        u64 r2 = mul2_(dx, dx);
        r2 = fma2_(dy, dy, r2);
        r2 = fma2_(dz, dz, r2);
        float r2a, r2b; upk2(r2, r2a, r2b);
        u64 invp = pk2(rsq_(r2a), rsq_(r2b));   // MUFU.RSQ x2
        u64 i2  = mul2_(invp, invp);
        u64 i4  = mul2_(i2, i2);
        u64 i5  = mul2_(i4, invp);
        u64 arg = mul2_(i5, C2);                // Cb * inv^5
        float aa, ab; upk2(arg, aa, ab);
        u64 ep = pk2(ex2f(aa), ex2f(ab));       // MUFU.EX2 x2
        u64 s  = fma2_(ep, H2, NH2);            // fr = 0.5*e - 0.5
        axp = fma2_(s, dx, axp);
        ayp = fma2_(s, dy, ayp);
        azp = fma2_(s, dz, azp);
    }

    float alo, ahi;
    upk2(axp, alo, ahi); red[w][0][lane] = alo + ahi;
    upk2(ayp, alo, ahi); red[w][1][lane] = alo + ahi;
    upk2(azp, alo, ahi); red[w][2][lane] = alo + ahi;
    __syncthreads();

    // Cross-warp reduce (fixed order). Rank 0 keeps it local; rank 1 pushes
    // its partial into rank 0's p1buf via DSMEM.
    const int t = threadIdx.x;
    if (t < 3 * ITILE) {
        const int d  = t / ITILE;
        const int il = t % ITILE;
        float s = 0.0f;
        #pragma unroll
        for (int ww = 0; ww < NWARP; ++ww) s += red[ww][d][il];
        if (half == 0) {
            fin[d][il] = s;
        } else {
            uint32_t laddr = (uint32_t)__cvta_generic_to_shared(&p1buf[d][il]);
            uint32_t raddr;
            asm("mapa.shared::cluster.u32 %0, %1, %2;" : "=r"(raddr) : "r"(laddr), "r"(0));
            asm volatile("st.shared::cluster.f32 [%0], %1;" :: "r"(raddr), "f"(s));
        }
    }

    // Cluster barrier: arrive(release) / wait(acquire) orders the DSMEM stores.
    asm volatile("barrier.cluster.arrive.aligned;" ::: "memory");
    asm volatile("barrier.cluster.wait.aligned;" ::: "memory");

    // Rank 0 combines (p0 + p1, fixed order) and writes the output.
    if (half == 0 && t < 3 * ITILE) {
        const int d  = t / ITILE;
        const int il = t % ITILE;
        const int ig = itile * ITILE + il;
        float s = fin[d][il] + p1buf[d][il];
        out[(pbase + ig) * 3 + d] = Lf * (uio[d][il] + s);
    }
}

extern "C" void kernel_launch(void* const* d_in, const int* in_sizes, int n_in,
                              void* d_out, int out_size) {
    const float* x = (const float*)d_in[0];
    float* out = (float*)d_out;

    const double Ld = pow((double)NPART / 0.016355, 1.0 / 3.0);
    const float  Lf    = (float)Ld;
    const float  invLf = (float)(1.0 / Ld);
    const double b5L   = pow(2.6 / Ld, 5.0);                 // (b/L)^5
    const float  Cb    = (float)(-b5L * 1.4426950408889634); // -(b/L)^5 * log2(e)

    backflow_kernel<<<NBLK, TPB>>>(x, out, Lf, invLf, Cb);
}

// round 8
// speedup vs baseline: 1.4928x; 1.4928x over previous
#include <cuda_runtime.h>
#include <math.h>

// Backflow transform, periodic box — 3-kernel pipeline, thin aux kernels.
//   prep:   u = -wrap(x)/L per SCALAR coordinate (49K threads) -> g_u (SoA)
//   main:   grid 1024 = 8 batches x 64 i-tiles x 2 j-halves, TPB 128, occ 8
//           packed f32x2 inner loop (2 j per lane), partial sums -> g_p
//   fixup:  out = L * (u_i + p0 + p1)  per scalar (deterministic fixed order)
// fr(d) = 0.5*(exp(-(b/d)^5) - 1); exp via 2^(Cb * rsqrt(r2u)^5), box units,
// Cb = -(b/L)^5*log2(e). Diagonal: r2=0 -> ex2(-inf)=0 -> s=-0.5, times 0 -> 0.
// rint via magic 1.5*2^23 (exact RNE for |t|<1; |du|<1 in box units).

#define NPART  2048
#define NBATCH 8
#define TPB    128
#define NWARP  4                         // warps per block
#define ITILE  32                        // i rows per block (one per lane)
#define JHALF  (NPART / 2)               // 1024 j's per block
#define JW     (JHALF / NWARP)           // 256 j's per warp -> 128 packed iters
#define NTILE  (NPART / ITILE)           // 64 i-tiles per batch
#define NBLK   (NBATCH * NTILE * 2)      // 1024 main blocks

typedef unsigned long long u64;

__device__ float g_u[3][NBATCH * NPART];        // negated wrapped coords / L (SoA)
__device__ float g_p[NBLK][3][ITILE];           // per-block partial sums (box units)

__device__ __forceinline__ u64 pk2(float lo, float hi) {
    u64 r; asm("mov.b64 %0, {%1,%2};" : "=l"(r) : "f"(lo), "f"(hi)); return r;
}
__device__ __forceinline__ void upk2(u64 v, float& lo, float& hi) {
    asm("mov.b64 {%0,%1}, %2;" : "=f"(lo), "=f"(hi) : "l"(v));
}
__device__ __forceinline__ u64 fma2_(u64 a, u64 b, u64 c) {
    u64 d; asm("fma.rn.f32x2 %0,%1,%2,%3;" : "=l"(d) : "l"(a), "l"(b), "l"(c)); return d;
}
__device__ __forceinline__ u64 add2_(u64 a, u64 b) {
    u64 d; asm("add.rn.f32x2 %0,%1,%2;" : "=l"(d) : "l"(a), "l"(b)); return d;
}
__device__ __forceinline__ u64 sub2_(u64 a, u64 b) {
    u64 d; asm("sub.rn.f32x2 %0,%1,%2;" : "=l"(d) : "l"(a), "l"(b)); return d;
}
__device__ __forceinline__ u64 mul2_(u64 a, u64 b) {
    u64 d; asm("mul.rn.f32x2 %0,%1,%2;" : "=l"(d) : "l"(a), "l"(b)); return d;
}
__device__ __forceinline__ float ex2f(float x) {
    float r; asm("ex2.approx.ftz.f32 %0, %1;" : "=f"(r) : "f"(x)); return r;
}
__device__ __forceinline__ float rsq_(float x) {
    float r; asm("rsqrt.approx.ftz.f32 %0, %1;" : "=f"(r) : "f"(x)); return r;
}

#define MAGICF 12582912.0f  // 1.5 * 2^23

// ---------- prep: one thread per scalar coordinate ----------
__global__ void prep_kernel(const float* __restrict__ x, float Lf, float invLf) {
    int g = blockIdx.x * blockDim.x + threadIdx.x;     // 0 .. NBATCH*NPART*3-1
    if (g < NBATCH * NPART * 3) {
        const int d = g % 3;
        const int p = g / 3;
        float v = x[g];
        v -= Lf * floorf(v / Lf);                      // divide matches reference
        g_u[d][p] = -v * invLf;
    }
}

// ---------- main: O(N^2/2) pair loop per block (identical to R6) ----------
__global__ __launch_bounds__(TPB, 8) void backflow_kernel(float Cb) {
    __shared__ __align__(16) float sx[JHALF];   // this block's j-half (negated, box units)
    __shared__ __align__(16) float sy[JHALF];
    __shared__ __align__(16) float sz[JHALF];
    __shared__ float red[NWARP][3][ITILE];

    const int blk   = blockIdx.x;
    const int b     = blk >> 7;                 // batch
    const int rem   = blk & 127;
    const int itile = rem >> 1;
    const int half  = rem & 1;
    const int pbase = b * NPART;
    const int jbase = pbase + half * JHALF;

    // Fill smem with this block's j-half (vectorized copy).
    {
        const float4* g0 = (const float4*)&g_u[0][jbase];
        const float4* g1 = (const float4*)&g_u[1][jbase];
        const float4* g2 = (const float4*)&g_u[2][jbase];
        float4* s0 = (float4*)sx; float4* s1 = (float4*)sy; float4* s2 = (float4*)sz;
        #pragma unroll
        for (int k = threadIdx.x; k < JHALF / 4; k += TPB) {
            s0[k] = g0[k]; s1[k] = g1[k]; s2[k] = g2[k];
        }
    }

    const int lane = threadIdx.x & 31;
    const int w    = threadIdx.x >> 5;          // 0..NWARP-1
    const int ig   = pbase + itile * ITILE + lane;

    const float ux = -g_u[0][ig];               // xi (positive, box units)
    const float uy = -g_u[1][ig];
    const float uz = -g_u[2][ig];
    __syncthreads();

    const u64 xix = pk2(ux, ux);
    const u64 xiy = pk2(uy, uy);
    const u64 xiz = pk2(uz, uz);
    const u64 MAG2  = pk2(MAGICF, MAGICF);
    const u64 NMAG2 = pk2(-MAGICF, -MAGICF);
    const u64 C2    = pk2(Cb, Cb);
    const u64 H2    = pk2(0.5f, 0.5f);
    const u64 NH2   = pk2(-0.5f, -0.5f);

    const u64* __restrict__ sx2 = (const u64*)sx;
    const u64* __restrict__ sy2 = (const u64*)sy;
    const u64* __restrict__ sz2 = (const u64*)sz;

    u64 axp = 0ull, ayp = 0ull, azp = 0ull;

    const int base = (w * JW) >> 1;
    #pragma unroll 4
    for (int jj = 0; jj < JW / 2; ++jj) {
        // All lanes read the same address -> LDS.64 broadcast, conflict-free.
        u64 nxj = sx2[base + jj];               // (-uj0, -uj1)
        u64 nyj = sy2[base + jj];
        u64 nzj = sz2[base + jj];
        u64 dx = add2_(xix, nxj);               // ui - uj, two pairs at once
        u64 dy = add2_(xiy, nyj);
        u64 dz = add2_(xiz, nzj);
        // minimum image in box units: d -= rint(d)
        u64 tx = add2_(dx, MAG2);
        u64 ty = add2_(dy, MAG2);
        u64 tz = add2_(dz, MAG2);
        u64 rx = add2_(tx, NMAG2);
        u64 ry = add2_(ty, NMAG2);
        u64 rz = add2_(tz, NMAG2);
        dx = sub2_(dx, rx);
        dy = sub2_(dy, ry);
        dz = sub2_(dz, rz);
        u64 r2 = mul2_(dx, dx);
        r2 = fma2_(dy, dy, r2);
        r2 = fma2_(dz, dz, r2);
        float r2a, r2b; upk2(r2, r2a, r2b);
        u64 invp = pk2(rsq_(r2a), rsq_(r2b));   // MUFU.RSQ x2
        u64 i2  = mul2_(invp, invp);
        u64 i4  = mul2_(i2, i2);
        u64 i5  = mul2_(i4, invp);
        u64 arg = mul2_(i5, C2);                // Cb * inv^5
        float aa, ab; upk2(arg, aa, ab);
        u64 ep = pk2(ex2f(aa), ex2f(ab));       // MUFU.EX2 x2
        u64 s  = fma2_(ep, H2, NH2);            // fr = 0.5*e - 0.5
        axp = fma2_(s, dx, axp);
        ayp = fma2_(s, dy, ayp);
        azp = fma2_(s, dz, azp);
    }

    float alo, ahi;
    upk2(axp, alo, ahi); red[w][0][lane] = alo + ahi;
    upk2(ayp, alo, ahi); red[w][1][lane] = alo + ahi;
    upk2(azp, alo, ahi); red[w][2][lane] = alo + ahi;
    __syncthreads();

    const int t = threadIdx.x;
    if (t < 3 * ITILE) {
        const int d  = t / ITILE;
        const int il = t % ITILE;
        float s = 0.0f;
        #pragma unroll
        for (int ww = 0; ww < NWARP; ++ww) s += red[ww][d][il];
        g_p[blk][d][il] = s;
    }
}

// ---------- fixup: combine the two j-half partials, write output ----------
__global__ void fixup_kernel(float* __restrict__ out, float Lf) {
    int g = blockIdx.x * blockDim.x + threadIdx.x;     // 0 .. NBATCH*NPART*3-1
    if (g < NBATCH * NPART * 3) {
        const int d  = g % 3;
        const int p  = g / 3;                          // global particle index
        const int b  = p / NPART;
        const int pi = p % NPART;
        const int itile = pi / ITILE;
        const int il    = pi % ITILE;
        const int blk0  = ((b * NTILE + itile) << 1);
        // Issue all three loads up front (MLP), then combine in fixed order.
        float p0 = g_p[blk0][d][il];
        float p1 = g_p[blk0 + 1][d][il];
        float u  = -g_u[d][p];
        out[g] = Lf * (u + (p0 + p1));
    }
}

extern "C" void kernel_launch(void* const* d_in, const int* in_sizes, int n_in,
                              void* d_out, int out_size) {
    const float* x = (const float*)d_in[0];
    float* out = (float*)d_out;

    const double Ld = pow((double)NPART / 0.016355, 1.0 / 3.0);
    const float  Lf    = (float)Ld;
    const float  invLf = (float)(1.0 / Ld);
    const double b5L   = pow(2.6 / Ld, 5.0);                 // (b/L)^5
    const float  Cb    = (float)(-b5L * 1.4426950408889634); // -(b/L)^5 * log2(e)

    const int NS = NBATCH * NPART * 3;                       // 49152 scalars
    prep_kernel<<<(NS + 255) / 256, 256>>>(x, Lf, invLf);
    backflow_kernel<<<NBLK, TPB>>>(Cb);
    fixup_kernel<<<(NS + 255) / 256, 256>>>(out, Lf);
}